// round 11
// baseline (speedup 1.0000x reference)
#include <cuda_runtime.h>

#define IN_DIM 768
#define OUT_DIM 768
#define BATCH 32
#define NUMF 8
#define NROWS 9                    // 8 sin rows + 1 silu row

#define CHUNK 8                    // i's per block
#define NSPLIT (IN_DIM / CHUNK)    // 96 k-splits
#define O_TILE 128
#define THREADS 256                // 8 warps: bg = warp&3, j-half = warp>>2
#define WSTRIDE 68                 // floats/row; 68%32==4 -> lanes tile all banks
#define TSTRIDE 34                 // transpose smem row stride (even -> 8B-aligned pairs)

typedef unsigned long long u64;

// ---- f32x2 helpers ----
__device__ __forceinline__ u64 pk2(float v) {
    u64 r; asm("mov.b64 %0, {%1, %1};" : "=l"(r) : "f"(v)); return r;
}
__device__ __forceinline__ u64 pk2ab(float a, float b) {
    u64 r; asm("mov.b64 %0, {%1, %2};" : "=l"(r) : "f"(a), "f"(b)); return r;
}
__device__ __forceinline__ void fma2(u64& d, u64 a, u64 b) {
    asm("fma.rn.f32x2 %0, %1, %2, %0;" : "+l"(d) : "l"(a), "l"(b));
}
__device__ __forceinline__ u64 mul2(u64 a, u64 b) {
    u64 r; asm("mul.rn.f32x2 %0, %1, %2;" : "=l"(r) : "l"(a), "l"(b)); return r;
}
__device__ __forceinline__ void redg_v4(float* addr, float a, float b, float c, float d) {
    asm volatile("red.global.add.v4.f32 [%0], {%1, %2, %3, %4};"
                 :: "l"(addr), "f"(a), "f"(b), "f"(c), "f"(d) : "memory");
}

// -------- Kernel G: fused basis + skinny GEMM + atomic epilogue --------
// Warp w: bg = w&3 (batch-group of 8), jh = w>>2 (o-half). Lane = o.
// Thread tile: 2 o x 8 b. s-row loads warp-uniform -> smem broadcast.
__global__ __launch_bounds__(THREADS, 4) void gemm_kernel(
    const float* __restrict__ x,
    const float* __restrict__ grid,
    const float* __restrict__ coef,
    const float* __restrict__ scale_sp,
    const float* __restrict__ scale_base,
    const float* __restrict__ bias_w,
    float* __restrict__ y) {

    __shared__ __align__(16) float stile[CHUNK * NROWS * BATCH];    // 9216 B
    __shared__ __align__(16) float wtile[O_TILE * WSTRIDE];         // 34816 B (reused for transpose)
    __shared__ float sbtile[O_TILE * 9];                            // 4608 B (stride 9)

    int tid = threadIdx.x;
    int lane = tid & 31;
    int warp = tid >> 5;
    int split = blockIdx.y;
    int i0 = split * CHUNK;
    int oBase = blockIdx.x * O_TILE;

    // ---- fused basis: each thread computes one (ii, b) column ----
    {
        int ii = tid >> 5;        // 0..7
        int b = tid & 31;
        float xv = x[b * IN_DIM + i0 + ii];
        float* col = stile + ii * (NROWS * BATCH) + b;

        float theta = __ldg(grid) * xv;
        float s1 = __sinf(theta);
        float c2 = 2.0f * __cosf(theta);
        float sm1 = s1, sm2 = 0.0f;
        col[0] = s1;
#pragma unroll
        for (int k = 1; k < NUMF; k++) {
            float sk = fmaf(c2, sm1, -sm2);
            sm2 = sm1; sm1 = sk;
            col[k * BATCH] = sk;
        }
        col[NUMF * BATCH] = xv / (1.0f + __expf(-xv));   // silu
    }

    // ---- stage w pre-scaled by scale_sp (packed f32x2 folds) ----
#pragma unroll
    for (int f = tid; f < O_TILE * CHUNK; f += THREADS) {   // 1024 granules, 4/thread
        int o_l = f >> 3;
        int i_l = f & 7;
        int idx = (oBase + o_l) * IN_DIM + i0 + i_l;
        float4 c0 = reinterpret_cast<const float4*>(coef)[idx * 2];
        float4 c1 = reinterpret_cast<const float4*>(coef)[idx * 2 + 1];
        u64 sp2 = pk2(__ldg(scale_sp + idx));
        u64 v0 = mul2(pk2ab(c0.x, c0.y), sp2);
        u64 v1 = mul2(pk2ab(c0.z, c0.w), sp2);
        u64 v2 = mul2(pk2ab(c1.x, c1.y), sp2);
        u64 v3 = mul2(pk2ab(c1.z, c1.w), sp2);
        u64* wp = reinterpret_cast<u64*>(wtile + o_l * WSTRIDE + i_l * 8);
        wp[0] = v0; wp[1] = v1; wp[2] = v2; wp[3] = v3;
    }
#pragma unroll
    for (int f = tid; f < O_TILE * CHUNK; f += THREADS) {
        int o_l = f >> 3;
        int ii = f & 7;
        sbtile[o_l * 9 + ii] =
            __ldg(scale_base + (oBase + o_l) * IN_DIM + i0 + ii);
    }
    __syncthreads();

    int bg = warp & 3;
    int jh = warp >> 2;           // o-half: rows (jh*2+j)*32+lane
    int b0 = bg * 8;
    const float* sbase = stile + b0;

    u64 acc[2][4];
#pragma unroll
    for (int j = 0; j < 2; j++)
#pragma unroll
        for (int p = 0; p < 4; p++) acc[j][p] = 0ULL;

#pragma unroll 2
    for (int ii = 0; ii < CHUNK; ii++) {
        const float* srow = sbase + ii * (NROWS * BATCH);

#pragma unroll
        for (int half = 0; half < 2; half++) {
            float4 w4[2];
#pragma unroll
            for (int j = 0; j < 2; j++)
                w4[j] = *reinterpret_cast<const float4*>(
                    wtile + ((jh * 2 + j) * 32 + lane) * WSTRIDE + ii * 8 + half * 4);

#pragma unroll
            for (int kk = 0; kk < 4; kk++) {
                int k = half * 4 + kk;
                const double2* s2p = reinterpret_cast<const double2*>(srow + k * BATCH);
                double2 sa = s2p[0], sb = s2p[1];       // warp-uniform -> broadcast
                u64 s[4] = {__double_as_longlong(sa.x), __double_as_longlong(sa.y),
                            __double_as_longlong(sb.x), __double_as_longlong(sb.y)};
#pragma unroll
                for (int j = 0; j < 2; j++) {
                    float wv = (kk == 0) ? w4[j].x : (kk == 1) ? w4[j].y
                             : (kk == 2) ? w4[j].z : w4[j].w;
                    u64 wk = pk2(wv);
#pragma unroll
                    for (int p = 0; p < 4; p++) fma2(acc[j][p], wk, s[p]);
                }
            }
        }
        // silu row with scale_base weights
        {
            const double2* s2p = reinterpret_cast<const double2*>(srow + NUMF * BATCH);
            double2 sa = s2p[0], sb = s2p[1];
            u64 s[4] = {__double_as_longlong(sa.x), __double_as_longlong(sa.y),
                        __double_as_longlong(sb.x), __double_as_longlong(sb.y)};
#pragma unroll
            for (int j = 0; j < 2; j++) {
                u64 wb = pk2(sbtile[((jh * 2 + j) * 32 + lane) * 9 + ii]);
#pragma unroll
                for (int p = 0; p < 4; p++) fma2(acc[j][p], wb, s[p]);
            }
        }
    }

    // ---- epilogue: smem transpose -> o-contiguous vector reductions into y ----
    __syncthreads();                       // done reading wtile; reuse as [o(128)][TSTRIDE]
#pragma unroll
    for (int j = 0; j < 2; j++) {
        int o_row = (jh * 2 + j) * 32 + lane;
#pragma unroll
        for (int p = 0; p < 4; p++) {
            // pair (b0+2p, b0+2p+1): even float offset -> 8B-aligned
            *reinterpret_cast<u64*>(wtile + o_row * TSTRIDE + b0 + 2 * p) = acc[j][p];
        }
    }
    __syncthreads();

    {
        int b = tid >> 3;                  // 0..31
        int o0 = (tid & 7) * 16;           // 16 consecutive o's
        float v[16];
#pragma unroll
        for (int q = 0; q < 16; q++)
            v[q] = wtile[(o0 + q) * TSTRIDE + b];

        if (split == 0) {                  // fold bias exactly once per (b, o)
            const float4* bp4 = reinterpret_cast<const float4*>(bias_w + oBase + o0);
#pragma unroll
            for (int m = 0; m < 4; m++) {
                float4 bv = bp4[m];
                v[4 * m + 0] += bv.x; v[4 * m + 1] += bv.y;
                v[4 * m + 2] += bv.z; v[4 * m + 3] += bv.w;
            }
        }

        float* dst = y + b * OUT_DIM + oBase + o0;
#pragma unroll
        for (int m = 0; m < 4; m++)
            redg_v4(dst + 4 * m, v[4 * m], v[4 * m + 1], v[4 * m + 2], v[4 * m + 3]);
    }
}

extern "C" void kernel_launch(void* const* d_in, const int* in_sizes, int n_in,
                              void* d_out, int out_size) {
    // metadata order: x, grid, coef, bias_w, scale_base, scale_sp
    const float* x          = (const float*)d_in[0];
    const float* grid       = (const float*)d_in[1];
    const float* coef       = (const float*)d_in[2];
    const float* bias_w     = (const float*)d_in[3];
    const float* scale_base = (const float*)d_in[4];
    const float* scale_sp   = (const float*)d_in[5];
    float* y = (float*)d_out;

    cudaMemsetAsync(y, 0, (size_t)out_size * sizeof(float));
    dim3 g(OUT_DIM / O_TILE, NSPLIT);   // 6 x 96 = 576 blocks, ~one wave at 4/SM
    gemm_kernel<<<g, THREADS>>>(x, grid, coef, scale_sp, scale_base, bias_w, y);
}

// round 12
// speedup vs baseline: 1.0935x; 1.0935x over previous
#include <cuda_runtime.h>

#define IN_DIM 768
#define OUT_DIM 768
#define BATCH 32
#define NUMF 8
#define NROWS 9                    // 8 sin rows + 1 silu row

#define CHUNK 8                    // i's per block
#define NSPLIT (IN_DIM / CHUNK)    // 96 k-splits
#define O_TILE 128
#define THREADS 256                // 8 warps: bg = warp&3, j-half = warp>>2
#define WSTRIDE 68                 // floats/row; 68%32==4 -> lanes tile all banks

typedef unsigned long long u64;

// ---- f32x2 helpers ----
__device__ __forceinline__ u64 pk2(float v) {
    u64 r; asm("mov.b64 %0, {%1, %1};" : "=l"(r) : "f"(v)); return r;
}
__device__ __forceinline__ u64 pk2ab(float a, float b) {
    u64 r; asm("mov.b64 %0, {%1, %2};" : "=l"(r) : "f"(a), "f"(b)); return r;
}
__device__ __forceinline__ void upk2(u64 v, float& lo, float& hi) {
    asm("mov.b64 {%0, %1}, %2;" : "=f"(lo), "=f"(hi) : "l"(v));
}
__device__ __forceinline__ void fma2(u64& d, u64 a, u64 b) {
    asm("fma.rn.f32x2 %0, %1, %2, %0;" : "+l"(d) : "l"(a), "l"(b));
}
__device__ __forceinline__ u64 mul2(u64 a, u64 b) {
    u64 r; asm("mul.rn.f32x2 %0, %1, %2;" : "=l"(r) : "l"(a), "l"(b)); return r;
}
__device__ __forceinline__ void redg_f32(float* addr, float v) {
    asm volatile("red.global.add.f32 [%0], %1;" :: "l"(addr), "f"(v) : "memory");
}

// -------- Kernel G: fused basis + skinny GEMM + direct coalesced REDG epilogue --------
// Warp w: bg = w&3 (batch-group of 8), jh = w>>2 (o-half). Lane = o.
// Thread tile: 2 o x 8 b. s-row loads warp-uniform -> smem broadcast.
__global__ __launch_bounds__(THREADS, 4) void gemm_kernel(
    const float* __restrict__ x,
    const float* __restrict__ grid,
    const float* __restrict__ coef,
    const float* __restrict__ scale_sp,
    const float* __restrict__ scale_base,
    const float* __restrict__ bias_w,
    float* __restrict__ y) {

    __shared__ __align__(16) float stile[CHUNK * NROWS * BATCH];    // 9216 B
    __shared__ __align__(16) float wtile[O_TILE * WSTRIDE];         // 34816 B
    __shared__ float sbtile[O_TILE * 9];                            // 4608 B (stride 9)

    int tid = threadIdx.x;
    int lane = tid & 31;
    int warp = tid >> 5;
    int split = blockIdx.y;
    int i0 = split * CHUNK;
    int oBase = blockIdx.x * O_TILE;

    // ---- fused basis: each thread computes one (ii, b) column ----
    {
        int ii = tid >> 5;        // 0..7
        int b = tid & 31;
        float xv = x[b * IN_DIM + i0 + ii];
        float* col = stile + ii * (NROWS * BATCH) + b;

        float theta = __ldg(grid) * xv;
        float s1 = __sinf(theta);
        float c2 = 2.0f * __cosf(theta);
        float sm1 = s1, sm2 = 0.0f;
        col[0] = s1;
#pragma unroll
        for (int k = 1; k < NUMF; k++) {
            float sk = fmaf(c2, sm1, -sm2);
            sm2 = sm1; sm1 = sk;
            col[k * BATCH] = sk;
        }
        col[NUMF * BATCH] = xv / (1.0f + __expf(-xv));   // silu
    }

    // ---- stage w pre-scaled by scale_sp (packed f32x2 folds) ----
#pragma unroll
    for (int f = tid; f < O_TILE * CHUNK; f += THREADS) {   // 1024 granules, 4/thread
        int o_l = f >> 3;
        int i_l = f & 7;
        int idx = (oBase + o_l) * IN_DIM + i0 + i_l;
        float4 c0 = reinterpret_cast<const float4*>(coef)[idx * 2];
        float4 c1 = reinterpret_cast<const float4*>(coef)[idx * 2 + 1];
        u64 sp2 = pk2(__ldg(scale_sp + idx));
        u64 v0 = mul2(pk2ab(c0.x, c0.y), sp2);
        u64 v1 = mul2(pk2ab(c0.z, c0.w), sp2);
        u64 v2 = mul2(pk2ab(c1.x, c1.y), sp2);
        u64 v3 = mul2(pk2ab(c1.z, c1.w), sp2);
        u64* wp = reinterpret_cast<u64*>(wtile + o_l * WSTRIDE + i_l * 8);
        wp[0] = v0; wp[1] = v1; wp[2] = v2; wp[3] = v3;
    }
#pragma unroll
    for (int f = tid; f < O_TILE * CHUNK; f += THREADS) {
        int o_l = f >> 3;
        int ii = f & 7;
        sbtile[o_l * 9 + ii] =
            __ldg(scale_base + (oBase + o_l) * IN_DIM + i0 + ii);
    }
    __syncthreads();

    int bg = warp & 3;
    int jh = warp >> 2;           // o-half: rows (jh*2+j)*32+lane
    int b0 = bg * 8;
    const float* sbase = stile + b0;

    u64 acc[2][4];
#pragma unroll
    for (int j = 0; j < 2; j++)
#pragma unroll
        for (int p = 0; p < 4; p++) acc[j][p] = 0ULL;

#pragma unroll 2
    for (int ii = 0; ii < CHUNK; ii++) {
        const float* srow = sbase + ii * (NROWS * BATCH);

#pragma unroll
        for (int half = 0; half < 2; half++) {
            float4 w4[2];
#pragma unroll
            for (int j = 0; j < 2; j++)
                w4[j] = *reinterpret_cast<const float4*>(
                    wtile + ((jh * 2 + j) * 32 + lane) * WSTRIDE + ii * 8 + half * 4);

#pragma unroll
            for (int kk = 0; kk < 4; kk++) {
                int k = half * 4 + kk;
                const double2* s2p = reinterpret_cast<const double2*>(srow + k * BATCH);
                double2 sa = s2p[0], sb = s2p[1];       // warp-uniform -> broadcast
                u64 s[4] = {__double_as_longlong(sa.x), __double_as_longlong(sa.y),
                            __double_as_longlong(sb.x), __double_as_longlong(sb.y)};
#pragma unroll
                for (int j = 0; j < 2; j++) {
                    float wv = (kk == 0) ? w4[j].x : (kk == 1) ? w4[j].y
                             : (kk == 2) ? w4[j].z : w4[j].w;
                    u64 wk = pk2(wv);
#pragma unroll
                    for (int p = 0; p < 4; p++) fma2(acc[j][p], wk, s[p]);
                }
            }
        }
        // silu row with scale_base weights
        {
            const double2* s2p = reinterpret_cast<const double2*>(srow + NUMF * BATCH);
            double2 sa = s2p[0], sb = s2p[1];
            u64 s[4] = {__double_as_longlong(sa.x), __double_as_longlong(sa.y),
                        __double_as_longlong(sb.x), __double_as_longlong(sb.y)};
#pragma unroll
            for (int j = 0; j < 2; j++) {
                u64 wb = pk2(sbtile[((jh * 2 + j) * 32 + lane) * 9 + ii]);
#pragma unroll
                for (int p = 0; p < 4; p++) fma2(acc[j][p], wb, s[p]);
            }
        }
    }

    // ---- epilogue: direct coalesced scalar reductions into y ----
    // For fixed (j, p, parity): lane = o -> 32 consecutive y addresses (1 line set).
    // split 0 folds bias (each (b, o) owned by exactly one thread there).
#pragma unroll
    for (int j = 0; j < 2; j++) {
        int o = oBase + (jh * 2 + j) * 32 + lane;
        float bw = (split == 0) ? __ldg(bias_w + o) : 0.0f;
#pragma unroll
        for (int p = 0; p < 4; p++) {
            float lo, hi;
            upk2(acc[j][p], lo, hi);
            redg_f32(y + (b0 + 2 * p) * OUT_DIM + o, lo + bw);
            redg_f32(y + (b0 + 2 * p + 1) * OUT_DIM + o, hi + bw);
        }
    }
}

extern "C" void kernel_launch(void* const* d_in, const int* in_sizes, int n_in,
                              void* d_out, int out_size) {
    // metadata order: x, grid, coef, bias_w, scale_base, scale_sp
    const float* x          = (const float*)d_in[0];
    const float* grid       = (const float*)d_in[1];
    const float* coef       = (const float*)d_in[2];
    const float* bias_w     = (const float*)d_in[3];
    const float* scale_base = (const float*)d_in[4];
    const float* scale_sp   = (const float*)d_in[5];
    float* y = (float*)d_out;

    cudaMemsetAsync(y, 0, (size_t)out_size * sizeof(float));
    dim3 g(OUT_DIM / O_TILE, NSPLIT);   // 6 x 96 = 576 blocks
    gemm_kernel<<<g, THREADS>>>(x, grid, coef, scale_sp, scale_base, bias_w, y);
}

// round 14
// speedup vs baseline: 1.2220x; 1.1175x over previous
#include <cuda_runtime.h>

#define IN_DIM 768
#define OUT_DIM 768
#define BATCH 32
#define NUMF 8
#define NROWS 9                    // 8 sin rows + 1 silu row

#define CHUNK 8                    // i's per block
#define NSPLIT (IN_DIM / CHUNK)    // 96 k-splits
#define O_TILE 128
#define THREADS 128                // 4 warps: bh = warp&1 (16 b), jh = warp>>1 (o-half)
#define WSTRIDE 68                 // floats/row; 68%32==4 -> lanes tile all banks

typedef unsigned long long u64;

// ---- f32x2 helpers ----
__device__ __forceinline__ u64 pk2(float v) {
    u64 r; asm("mov.b64 %0, {%1, %1};" : "=l"(r) : "f"(v)); return r;
}
__device__ __forceinline__ u64 pk2ab(float a, float b) {
    u64 r; asm("mov.b64 %0, {%1, %2};" : "=l"(r) : "f"(a), "f"(b)); return r;
}
__device__ __forceinline__ void upk2(u64 v, float& lo, float& hi) {
    asm("mov.b64 {%0, %1}, %2;" : "=f"(lo), "=f"(hi) : "l"(v));
}
__device__ __forceinline__ void fma2(u64& d, u64 a, u64 b) {
    asm("fma.rn.f32x2 %0, %1, %2, %0;" : "+l"(d) : "l"(a), "l"(b));
}
__device__ __forceinline__ u64 mul2(u64 a, u64 b) {
    u64 r; asm("mul.rn.f32x2 %0, %1, %2;" : "=l"(r) : "l"(a), "l"(b)); return r;
}
__device__ __forceinline__ void redg_f32(float* addr, float v) {
    asm volatile("red.global.add.f32 [%0], %1;" :: "l"(addr), "f"(v) : "memory");
}

// -------- Kernel G: fused basis + skinny GEMM + coalesced REDG epilogue --------
// Warp w: bh = w&1 (16 batches), jh = w>>1 (o-half). Lane = o.
// Thread tile: 2 o x 16 b -> s-broadcast cost amortized over 2x more FMA.
__global__ __launch_bounds__(THREADS, 4) void gemm_kernel(
    const float* __restrict__ x,
    const float* __restrict__ grid,
    const float* __restrict__ coef,
    const float* __restrict__ scale_sp,
    const float* __restrict__ scale_base,
    const float* __restrict__ bias_w,
    float* __restrict__ y) {

    __shared__ __align__(16) float stile[CHUNK * NROWS * BATCH];    // 9216 B
    __shared__ __align__(16) float wtile[O_TILE * WSTRIDE];         // 34816 B
    __shared__ float sbtile[O_TILE * 9];                            // 4608 B (stride 9)

    int tid = threadIdx.x;
    int lane = tid & 31;
    int warp = tid >> 5;
    int split = blockIdx.y;
    int i0 = split * CHUNK;
    int oBase = blockIdx.x * O_TILE;

    // ---- fused basis: 256 (ii, b) columns, 2 per thread ----
    for (int f = tid; f < CHUNK * BATCH; f += THREADS) {
        int ii = f >> 5;
        int b = f & 31;
        float xv = x[b * IN_DIM + i0 + ii];
        float* col = stile + ii * (NROWS * BATCH) + b;

        float theta = __ldg(grid) * xv;
        float s1 = __sinf(theta);
        float c2 = 2.0f * __cosf(theta);
        float sm1 = s1, sm2 = 0.0f;
        col[0] = s1;
#pragma unroll
        for (int k = 1; k < NUMF; k++) {
            float sk = fmaf(c2, sm1, -sm2);
            sm2 = sm1; sm1 = sk;
            col[k * BATCH] = sk;
        }
        col[NUMF * BATCH] = xv / (1.0f + __expf(-xv));   // silu
    }

    // ---- stage w pre-scaled by scale_sp (packed f32x2 folds) ----
#pragma unroll
    for (int f = tid; f < O_TILE * CHUNK; f += THREADS) {   // 1024 granules, 8/thread
        int o_l = f >> 3;
        int i_l = f & 7;
        int idx = (oBase + o_l) * IN_DIM + i0 + i_l;
        float4 c0 = reinterpret_cast<const float4*>(coef)[idx * 2];
        float4 c1 = reinterpret_cast<const float4*>(coef)[idx * 2 + 1];
        u64 sp2 = pk2(__ldg(scale_sp + idx));
        u64 v0 = mul2(pk2ab(c0.x, c0.y), sp2);
        u64 v1 = mul2(pk2ab(c0.z, c0.w), sp2);
        u64 v2 = mul2(pk2ab(c1.x, c1.y), sp2);
        u64 v3 = mul2(pk2ab(c1.z, c1.w), sp2);
        u64* wp = reinterpret_cast<u64*>(wtile + o_l * WSTRIDE + i_l * 8);
        wp[0] = v0; wp[1] = v1; wp[2] = v2; wp[3] = v3;
    }
#pragma unroll
    for (int f = tid; f < O_TILE * CHUNK; f += THREADS) {
        int o_l = f >> 3;
        int ii = f & 7;
        sbtile[o_l * 9 + ii] =
            __ldg(scale_base + (oBase + o_l) * IN_DIM + i0 + ii);
    }
    __syncthreads();

    int bh = warp & 1;
    int jh = warp >> 1;           // o-half: rows (jh*2+j)*32+lane
    int b0 = bh * 16;             // this warp's 16 batches
    const float* sbase = stile + b0;

    u64 acc[2][8];
#pragma unroll
    for (int j = 0; j < 2; j++)
#pragma unroll
        for (int p = 0; p < 8; p++) acc[j][p] = 0ULL;

#pragma unroll 2
    for (int ii = 0; ii < CHUNK; ii++) {
        const float* srow = sbase + ii * (NROWS * BATCH);

        // two k-halves to cap register pressure
#pragma unroll
        for (int half = 0; half < 2; half++) {
            float4 w4[2];
#pragma unroll
            for (int j = 0; j < 2; j++)
                w4[j] = *reinterpret_cast<const float4*>(
                    wtile + ((jh * 2 + j) * 32 + lane) * WSTRIDE + ii * 8 + half * 4);

#pragma unroll
            for (int kk = 0; kk < 4; kk++) {
                int k = half * 4 + kk;
                const double2* s2p = reinterpret_cast<const double2*>(srow + k * BATCH);
                double2 sa = s2p[0], sb = s2p[1], sc = s2p[2], sd = s2p[3];
                u64 s[8] = {__double_as_longlong(sa.x), __double_as_longlong(sa.y),
                            __double_as_longlong(sb.x), __double_as_longlong(sb.y),
                            __double_as_longlong(sc.x), __double_as_longlong(sc.y),
                            __double_as_longlong(sd.x), __double_as_longlong(sd.y)};
#pragma unroll
                for (int j = 0; j < 2; j++) {
                    float wv = (kk == 0) ? w4[j].x : (kk == 1) ? w4[j].y
                             : (kk == 2) ? w4[j].z : w4[j].w;
                    u64 wk = pk2(wv);
#pragma unroll
                    for (int p = 0; p < 8; p++) fma2(acc[j][p], wk, s[p]);
                }
            }
        }
        // silu row with scale_base weights
        {
            const double2* s2p = reinterpret_cast<const double2*>(srow + NUMF * BATCH);
            double2 sa = s2p[0], sb = s2p[1], sc = s2p[2], sd = s2p[3];
            u64 s[8] = {__double_as_longlong(sa.x), __double_as_longlong(sa.y),
                        __double_as_longlong(sb.x), __double_as_longlong(sb.y),
                        __double_as_longlong(sc.x), __double_as_longlong(sc.y),
                        __double_as_longlong(sd.x), __double_as_longlong(sd.y)};
#pragma unroll
            for (int j = 0; j < 2; j++) {
                u64 wb = pk2(sbtile[((jh * 2 + j) * 32 + lane) * 9 + ii]);
#pragma unroll
                for (int p = 0; p < 8; p++) fma2(acc[j][p], wb, s[p]);
            }
        }
    }

    // ---- epilogue: direct coalesced scalar reductions into y ----
    // For fixed (j, p, parity): lane = o -> 32 consecutive y addresses.
#pragma unroll
    for (int j = 0; j < 2; j++) {
        int o = oBase + (jh * 2 + j) * 32 + lane;
        float bw = (split == 0) ? __ldg(bias_w + o) : 0.0f;
#pragma unroll
        for (int p = 0; p < 8; p++) {
            float lo, hi;
            upk2(acc[j][p], lo, hi);
            redg_f32(y + (b0 + 2 * p) * OUT_DIM + o, lo + bw);
            redg_f32(y + (b0 + 2 * p + 1) * OUT_DIM + o, hi + bw);
        }
    }
}

extern "C" void kernel_launch(void* const* d_in, const int* in_sizes, int n_in,
                              void* d_out, int out_size) {
    // metadata order: x, grid, coef, bias_w, scale_base, scale_sp
    const float* x          = (const float*)d_in[0];
    const float* grid       = (const float*)d_in[1];
    const float* coef       = (const float*)d_in[2];
    const float* bias_w     = (const float*)d_in[3];
    const float* scale_base = (const float*)d_in[4];
    const float* scale_sp   = (const float*)d_in[5];
    float* y = (float*)d_out;

    cudaMemsetAsync(y, 0, (size_t)out_size * sizeof(float));
    dim3 g(OUT_DIM / O_TILE, NSPLIT);   // 6 x 96 = 576 blocks
    gemm_kernel<<<g, THREADS>>>(x, grid, coef, scale_sp, scale_base, bias_w, y);
}